// round 8
// baseline (speedup 1.0000x reference)
#include <cuda_runtime.h>
#include <cuda_bf16.h>
#include <cstdint>

// ---------------- problem constants (fixed by setup_inputs) ----------------
#define NPTS   20000
#define NDST   5000
#define KNB    32

// FPS cluster config: 16-CTA cluster (nonportable size, one GPC)
#define FPS_B  16
#define FPS_T  256
#define PPT    3                              // pair-iters per thread
#define PTS_REAL  1250                        // NPTS / FPS_B
#define PAIRS_REAL 625
#define PTS_ALLOC (FPS_T * PPT * 2)           // 1536 (padded)
#define NWARP  8
#define NSLOT  (FPS_B * NWARP)                // 128 warp slots cluster-wide

// output layout (float32, concatenated in reference return order)
#define OFF_COORD 0
#define OFF_FEAT  15000
#define OFF_ESRC  655000
#define OFF_EDST  815000
#define OFF_DEG   975000
#define OFF_BATCH 980000

static __device__ float g_ssrc[NPTS];
static __device__ int   g_sel[NDST];
static __device__ int   g_nbr[NDST * KNB];
static __device__ int   g_deg[NDST];

typedef unsigned long long u64;

__device__ __forceinline__ u64 f2_add(u64 a, u64 b) {
    u64 r; asm("add.rn.f32x2 %0, %1, %2;" : "=l"(r) : "l"(a), "l"(b)); return r;
}
__device__ __forceinline__ u64 f2_mul(u64 a, u64 b) {
    u64 r; asm("mul.rn.f32x2 %0, %1, %2;" : "=l"(r) : "l"(a), "l"(b)); return r;
}
__device__ __forceinline__ u64 f2_pack(float lo, float hi) {
    u64 r; asm("mov.b64 %0, {%1, %2};" : "=l"(r) : "f"(lo), "f"(hi)); return r;
}
__device__ __forceinline__ float2 f2_unpack(u64 a) {
    float2 v; asm("mov.b64 {%0, %1}, %2;" : "=f"(v.x), "=f"(v.y) : "l"(a)); return v;
}
__device__ __forceinline__ u64 lds_rlx(uint32_t a) {
    u64 v; asm volatile("ld.relaxed.cluster.shared::cta.u64 %0, [%1];" : "=l"(v) : "r"(a));
    return v;
}
__device__ __forceinline__ void st_remote(uint32_t ra, u64 v) {
    asm volatile("st.relaxed.cluster.shared::cluster.u64 [%0], %1;" :: "r"(ra), "l"(v) : "memory");
}
__device__ __forceinline__ uint32_t mapa_rank(uint32_t la, uint32_t rank) {
    uint32_t ra;
    asm("mapa.shared::cluster.u32 %0, %1, %2;" : "=r"(ra) : "r"(la), "r"(rank));
    return ra;
}

// reference-order squared distance: ((dx*dx + dy*dy) + dz*dz), no fma
__device__ __forceinline__ float d2_ref(float x, float y, float z,
                                        float cx, float cy, float cz) {
    float dx = __fsub_rn(x, cx), dy = __fsub_rn(y, cy), dz = __fsub_rn(z, cz);
    return __fadd_rn(__fadd_rn(__fmul_rn(dx, dx), __fmul_rn(dy, dy)),
                     __fmul_rn(dz, dz));
}

// ---------------- sum of squares per src point ----------------
__global__ void ssrc_kernel(const float* __restrict__ coord) {
    int j = blockIdx.x * blockDim.x + threadIdx.x;
    if (j < NPTS) {
        float x = coord[3 * j], y = coord[3 * j + 1], z = coord[3 * j + 2];
        g_ssrc[j] = __fadd_rn(__fadd_rn(__fmul_rn(x, x), __fmul_rn(y, y)),
                              __fmul_rn(z, z));
    }
}

// ---------------- FPS: 16-CTA cluster, warp-synchronous all-to-all ---------
// Key layout: [59:47] iter tag | [46:15] value f32 bits | [14:0] 0x7fff - idx
// Coord slot: [63:32] iter tag | [31:0] f32 bits
// Slot group (32B) per (parity, cta, warp): [key, x, y, z]
__global__ __launch_bounds__(FPS_T, 1) __cluster_dims__(FPS_B, 1, 1)
void fps_kernel(const float* __restrict__ coord, float* __restrict__ out) {
    __shared__ float sXX[PTS_ALLOC];
    __shared__ float sYY[PTS_ALLOC];
    __shared__ float sZZ[PTS_ALLOC];
    __shared__ u64 sSlot[2][NSLOT][4];

    const int t = threadIdx.x;
    const int b = blockIdx.x;              // cluster rank (grid = 1 cluster)
    const int warp = t >> 5;
    const int lane = t & 31;
    const int gbase = b * PTS_REAL;

    float mind[2 * PPT];
    u64   zp[PPT];

    // zero slots (tag 0 never matches iter >= 1): 1024 u64 over 256 threads
#pragma unroll
    for (int q = 0; q < 4; q++) ((u64*)sSlot)[t + q * 256] = 0ull;

    const float c0x = coord[0], c0y = coord[1], c0z = coord[2];
    float tmax = -1e30f;

#pragma unroll
    for (int k = 0; k < PPT; k++) {
        int p  = t + k * FPS_T;            // block-local pair
        int i0 = gbase + 2 * p;
        int i1 = i0 + 1;
        float x0, y0, z0, x1, y1, z1, m0, m1;
        if (p < PAIRS_REAL) {
            x0 = coord[3 * i0]; y0 = coord[3 * i0 + 1]; z0 = coord[3 * i0 + 2];
            m0 = d2_ref(x0, y0, z0, c0x, c0y, c0z);
            x1 = coord[3 * i1]; y1 = coord[3 * i1 + 1]; z1 = coord[3 * i1 + 2];
            m1 = d2_ref(x1, y1, z1, c0x, c0y, c0z);
        } else {
            x0 = y0 = z0 = x1 = y1 = z1 = 1e18f; m0 = m1 = -1.0f;
        }
        sXX[2 * p] = x0; sXX[2 * p + 1] = x1;
        sYY[2 * p] = y0; sYY[2 * p + 1] = y1;
        sZZ[2 * p] = z0; sZZ[2 * p + 1] = z1;
        zp[k] = f2_pack(z0, z1);
        mind[2 * k] = m0; mind[2 * k + 1] = m1;
        tmax = fmaxf(tmax, fmaxf(m0, m1));
    }

    // per-thread first-index of the max
    int bidx = 0x7FFF;
#pragma unroll
    for (int k = 0; k < PPT; k++) {
        int g = gbase + 2 * (t + k * FPS_T);
        if (mind[2 * k] == tmax && g < bidx)           bidx = g;
        if (mind[2 * k + 1] == tmax && (g + 1) < bidx) bidx = g + 1;
    }

    if (b == 0 && t == 0) {
        g_sel[0] = 0;
        out[OFF_COORD + 0] = c0x; out[OFF_COORD + 1] = c0y; out[OFF_COORD + 2] = c0z;
    }
    __syncthreads();
    // all CTAs' slot-zeroing + smem tiles visible before any remote publish
    asm volatile("barrier.cluster.arrive.aligned;" ::: "memory");
    asm volatile("barrier.cluster.wait.aligned;" ::: "memory");

    const uint32_t slotBase = (uint32_t)__cvta_generic_to_shared(&sSlot[0][0][0]);
    const int sid = b * NWARP + warp;      // this warp's cluster-wide slot id
    const uint32_t myOff = (uint32_t)sid * 32u;
    // publish fan-out: 64 store-ids (16 peers x 4 slots), 2 per lane
    const int p0 = lane >> 2,        s0 = lane & 3;          // ids 0..31
    const int p1 = (lane + 32) >> 2, s1 = lane & 3;          // ids 32..63

    for (int i = 1; i < NDST; i++) {
        // --- warp-level candidate (val, first-idx) via 32-bit redux ---
        unsigned vb = __float_as_uint(fmaxf(tmax, 0.0f));
        unsigned wm = __reduce_max_sync(0xffffffffu, vb);
        unsigned inv = (vb == wm) ? (unsigned)(0x7FFF - bidx) : 0u;
        unsigned wi = __reduce_max_sync(0xffffffffu, inv);
        const int widx = 0x7FFF - (int)wi;      // warp winner, global idx
        const int li = widx - gbase;            // local (this warp owns it)

        const uint32_t par = (uint32_t)(i & 1);
        const uint32_t parOff = par * (NSLOT * 32u);

        // --- publish key + winner coords to every CTA (2 stores per lane) ---
        {
            u64 vk = ((u64)(unsigned)i << 47) | ((u64)wm << 15) | (u64)wi;
            u64 v0, v1;
            if (s0 == 0) v0 = vk;
            else {
                float c = (s0 == 1) ? sXX[li] : (s0 == 2) ? sYY[li] : sZZ[li];
                v0 = ((u64)(unsigned)i << 32) | (u64)__float_as_uint(c);
            }
            v1 = v0;   // same slot id s, different peer
            uint32_t la = slotBase + parOff + myOff + (uint32_t)s0 * 8u;
            st_remote(mapa_rank(la, (uint32_t)p0), v0);
            st_remote(mapa_rank(la, (uint32_t)p1), v1);
        }

        // --- poll all 128 keys (4 per lane), ballot until complete ---
        const uint32_t gbuf = slotBase + parOff;
        const uint32_t a0 = gbuf + (uint32_t)lane * 32u;
        u64 k0, k1, k2, k3;
        for (;;) {
            k0 = lds_rlx(a0);
            k1 = lds_rlx(a0 + 32u * 32u);
            k2 = lds_rlx(a0 + 64u * 32u);
            k3 = lds_rlx(a0 + 96u * 32u);
            bool o = ((unsigned)(k0 >> 47) == (unsigned)i) &
                     ((unsigned)(k1 >> 47) == (unsigned)i) &
                     ((unsigned)(k2 >> 47) == (unsigned)i) &
                     ((unsigned)(k3 >> 47) == (unsigned)i);
            if (__all_sync(0xffffffffu, o)) break;
        }
        u64 ka = (k0 > k1) ? k0 : k1;
        u64 kb = (k2 > k3) ? k2 : k3;
        u64 k = (ka > kb) ? ka : kb;
        unsigned v32 = (unsigned)(k >> 15);        // value bits
        unsigned i15 = (unsigned)(k & 0x7FFFu);    // inv idx
        unsigned vmax = __reduce_max_sync(0xffffffffu, v32);
        unsigned imax = __reduce_max_sync(0xffffffffu, (v32 == vmax) ? i15 : 0u);
        const int sel = 0x7FFF - (int)imax;

        // --- winner's coord slots (arrive with its key; tag-checked) ---
        const int wc = sel / PTS_REAL;                 // owning rank
        const int lp = (sel - wc * PTS_REAL) >> 1;     // owning pair
        const int ww = (lp & (FPS_T - 1)) >> 5;        // owning warp
        const uint32_t cb = gbuf + (uint32_t)(wc * NWARP + ww) * 32u;
        u64 c1, c2, c3;
        for (;;) {
            c1 = lds_rlx(cb + 8u); c2 = lds_rlx(cb + 16u); c3 = lds_rlx(cb + 24u);
            bool o = ((unsigned)(c1 >> 32) == (unsigned)i) &
                     ((unsigned)(c2 >> 32) == (unsigned)i) &
                     ((unsigned)(c3 >> 32) == (unsigned)i);
            if (o) break;
        }
        const float cx = __uint_as_float((unsigned)c1);
        const float cy = __uint_as_float((unsigned)c2);
        const float cz = __uint_as_float((unsigned)c3);

        if (b == 0 && t == 0) {
            g_sel[i] = sel;
            out[OFF_COORD + 3 * i]     = cx;
            out[OFF_COORD + 3 * i + 1] = cy;
            out[OFF_COORD + 3 * i + 2] = cz;
        }

        // --- update min distances (packed f32x2; exact per-element rounding) ---
        const u64 ncx = f2_pack(-cx, -cx);
        const u64 ncy = f2_pack(-cy, -cy);
        const u64 ncz = f2_pack(-cz, -cz);
        float tA = -1e30f, tB = -1e30f;
#pragma unroll
        for (int kk = 0; kk < PPT; kk++) {
            int p = t + kk * FPS_T;
            u64 xx = *reinterpret_cast<const u64*>(&sXX[2 * p]);
            u64 yy = *reinterpret_cast<const u64*>(&sYY[2 * p]);
            u64 dx = f2_add(xx, ncx);
            u64 dy = f2_add(yy, ncy);
            u64 dz = f2_add(zp[kk], ncz);
            u64 d2 = f2_add(f2_add(f2_mul(dx, dx), f2_mul(dy, dy)), f2_mul(dz, dz));
            float2 d = f2_unpack(d2);
            mind[2 * kk]     = fminf(mind[2 * kk], d.x);
            mind[2 * kk + 1] = fminf(mind[2 * kk + 1], d.y);
            tA = fmaxf(tA, mind[2 * kk]);
            tB = fmaxf(tB, mind[2 * kk + 1]);
        }
        tmax = fmaxf(tA, tB);

        // per-thread first-index of new max
        bidx = 0x7FFF;
#pragma unroll
        for (int kk = 0; kk < PPT; kk++) {
            int g = gbase + 2 * (t + kk * FPS_T);
            if (mind[2 * kk] == tmax && g < bidx)           bidx = g;
            if (mind[2 * kk + 1] == tmax && (g + 1) < bidx) bidx = g + 1;
        }
    }

    // keep cluster resident until all remote traffic has been consumed
    asm volatile("barrier.cluster.arrive.aligned;" ::: "memory");
    asm volatile("barrier.cluster.wait.aligned;" ::: "memory");
}

// ---------------- ball query: one warp per dst, ordered append -------------
__global__ void ball_kernel(const float* __restrict__ coord,
                            const int* __restrict__ batch,
                            float* __restrict__ out) {
    __shared__ int sN[4][KNB];
    const int warp = threadIdx.x >> 5;
    const int lane = threadIdx.x & 31;
    const int d = blockIdx.x * 4 + warp;
    if (d >= NDST) return;

    const float R2 = (float)(0.08 * 0.08);
    const int sel = g_sel[d];
    const float cx = coord[3 * sel], cy = coord[3 * sel + 1], cz = coord[3 * sel + 2];
    const float sd = g_ssrc[sel];

    int cnt = 0;
    for (int j0 = 0; j0 < NPTS; j0 += 32) {
        const int j = j0 + lane;   // NPTS % 32 == 0, no tail
        float xj = coord[3 * j], yj = coord[3 * j + 1], zj = coord[3 * j + 2];
        float sj = g_ssrc[j];
        float dot = __fmaf_rn(cz, zj, __fmaf_rn(cy, yj, __fmul_rn(cx, xj)));
        float d2 = __fsub_rn(__fadd_rn(sd, sj), __fmul_rn(2.0f, dot));
        bool w = (d2 <= R2);
        unsigned bal = __ballot_sync(0xffffffffu, w);
        int pos = cnt + __popc(bal & ((1u << lane) - 1u));
        if (w && pos < KNB) sN[warp][pos] = j;
        cnt += __popc(bal);
        if (cnt >= KNB) break;
    }
    __syncwarp();

    const int deg = min(cnt, KNB);
    const int base = d * KNB;
    int nb = (lane < deg) ? sN[warp][lane] : -1;
    g_nbr[base + lane] = nb;
    out[OFF_ESRC + base + lane] = (float)nb;
    out[OFF_EDST + base + lane] = (lane < deg) ? (float)d : -1.0f;
    if (lane == 0) {
        g_deg[d] = deg;
        out[OFF_DEG + d] = (float)deg;
        out[OFF_BATCH + d] = (float)batch[sel];
    }
}

// ---------------- feature scatter-mean: one block (128 thr) per dst --------
__global__ void feat_kernel(const float* __restrict__ feat,
                            float* __restrict__ out) {
    __shared__ int sNbr[KNB];
    __shared__ int sDeg;
    const int d = blockIdx.x;
    const int tid = threadIdx.x;
    if (tid < KNB) sNbr[tid] = g_nbr[d * KNB + tid];
    if (tid == 0)  sDeg = g_deg[d];
    __syncthreads();
    const int dg = sDeg;
    float acc = 0.0f;
    for (int k = 0; k < dg; k++)
        acc = __fadd_rn(acc, feat[(size_t)sNbr[k] * 128 + tid]);
    out[OFF_FEAT + (size_t)d * 128 + tid] = acc / (float)max(dg, 1);
}

// ---------------- launch ----------------
extern "C" void kernel_launch(void* const* d_in, const int* in_sizes, int n_in,
                              void* d_out, int out_size) {
    const float* coord = (const float*)d_in[0];
    const float* feat  = (const float*)d_in[1];
    const int*   batch = (const int*)d_in[2];
    float* out = (float*)d_out;

    static int attr_done = 0;
    if (!attr_done) {
        cudaFuncSetAttribute(fps_kernel,
                             cudaFuncAttributeNonPortableClusterSizeAllowed, 1);
        attr_done = 1;
    }

    ssrc_kernel<<<(NPTS + 255) / 256, 256>>>(coord);
    fps_kernel<<<FPS_B, FPS_T>>>(coord, out);
    ball_kernel<<<(NDST + 3) / 4, 128>>>(coord, batch, out);
    feat_kernel<<<NDST, 128>>>(feat, out);
}

// round 9
// speedup vs baseline: 1.4063x; 1.4063x over previous
#include <cuda_runtime.h>
#include <cuda_bf16.h>
#include <cstdint>

// ---------------- problem constants (fixed by setup_inputs) ----------------
#define NPTS   20000
#define NDST   5000
#define KNB    32

// FPS cluster config (R7-proven): 8-CTA cluster + 136 overlapped ball CTAs
#define FPS_B  8
#define FPS_T  256
#define PPT    5                              // pairs per thread (10 points)
#define PTS_PER_BLOCK (FPS_T * PPT * 2)       // 2560
#define NWARP  8
#define NSLOT  (FPS_B * NWARP)                // 64 warp slots cluster-wide

#define BALL_CTAS 136
#define GRID_CTAS (FPS_B + BALL_CTAS)         // 144, multiple of 8
#define BALL_WARPS (BALL_CTAS * NWARP)        // 1088
#define DYN_SMEM (120 * 1024)                 // forces 1 CTA/SM

// output layout (float32, concatenated in reference return order)
#define OFF_COORD 0
#define OFF_FEAT  15000
#define OFF_ESRC  655000
#define OFF_EDST  815000
#define OFF_DEG   975000
#define OFF_BATCH 980000

static __device__ float g_ssrc[NPTS];
static __device__ int   g_sel[NDST];
static __device__ int   g_nbr[NDST * KNB];
static __device__ int   g_deg[NDST];

typedef unsigned long long u64;

__device__ __forceinline__ u64 f2_add(u64 a, u64 b) {
    u64 r; asm("add.rn.f32x2 %0, %1, %2;" : "=l"(r) : "l"(a), "l"(b)); return r;
}
__device__ __forceinline__ u64 f2_mul(u64 a, u64 b) {
    u64 r; asm("mul.rn.f32x2 %0, %1, %2;" : "=l"(r) : "l"(a), "l"(b)); return r;
}
__device__ __forceinline__ u64 f2_pack(float lo, float hi) {
    u64 r; asm("mov.b64 %0, {%1, %2};" : "=l"(r) : "f"(lo), "f"(hi)); return r;
}
__device__ __forceinline__ float2 f2_unpack(u64 a) {
    float2 v; asm("mov.b64 {%0, %1}, %2;" : "=f"(v.x), "=f"(v.y) : "l"(a)); return v;
}
__device__ __forceinline__ u64 lds_rlx(uint32_t a) {
    u64 v; asm volatile("ld.relaxed.cluster.shared::cta.u64 %0, [%1];" : "=l"(v) : "r"(a));
    return v;
}
__device__ __forceinline__ void st_remote(uint32_t ra, u64 v) {
    asm volatile("st.relaxed.cluster.shared::cluster.u64 [%0], %1;" :: "r"(ra), "l"(v) : "memory");
}
__device__ __forceinline__ uint32_t mapa_rank(uint32_t la, uint32_t rank) {
    uint32_t ra;
    asm("mapa.shared::cluster.u32 %0, %1, %2;" : "=r"(ra) : "r"(la), "r"(rank));
    return ra;
}
__device__ __forceinline__ int ld_rlx_i(const int* p) {
    int v; asm volatile("ld.relaxed.gpu.s32 %0, [%1];" : "=r"(v) : "l"(p)); return v;
}
__device__ __forceinline__ void st_rlx_i(int* p, int v) {
    asm volatile("st.relaxed.gpu.s32 [%0], %1;" :: "l"(p), "r"(v));
}

// reference-order squared distance: ((dx*dx + dy*dy) + dz*dz), no fma
__device__ __forceinline__ float d2_ref(float x, float y, float z,
                                        float cx, float cy, float cz) {
    float dx = __fsub_rn(x, cx), dy = __fsub_rn(y, cy), dz = __fsub_rn(z, cz);
    return __fadd_rn(__fadd_rn(__fmul_rn(dx, dx), __fmul_rn(dy, dy)),
                     __fmul_rn(dz, dz));
}

// ---------------- sum of squares per src point + g_sel reset ---------------
__global__ void ssrc_kernel(const float* __restrict__ coord) {
    int j = blockIdx.x * blockDim.x + threadIdx.x;
    if (j < NDST) g_sel[j] = -1;
    if (j < NPTS) {
        float x = coord[3 * j], y = coord[3 * j + 1], z = coord[3 * j + 2];
        g_ssrc[j] = __fadd_rn(__fadd_rn(__fmul_rn(x, x), __fmul_rn(y, y)),
                              __fmul_rn(z, z));
    }
}

// ---------------- fused FPS (CTAs 0-7) + polled ball query (CTAs 8-143) ----
// Key layout: [59:47] iter tag | [46:15] value f32 bits | [14:0] 0x7fff - idx
// Coord slot: [63:32] iter tag | [31:0] f32 bits
// Slot group (32B) per (parity, cta, warp): [key, x, y, z]
__global__ __launch_bounds__(FPS_T, 1) __cluster_dims__(FPS_B, 1, 1)
void fps_kernel(const float* __restrict__ coord,
                const int* __restrict__ batch,
                float* __restrict__ out) {
    extern __shared__ char dynsm[];
    __shared__ int sN[NWARP][KNB];         // ball path neighbor buffers

    const int t = threadIdx.x;
    const int b = blockIdx.x;
    const int warp = t >> 5;
    const int lane = t & 31;

    if (b < FPS_B) {
        // ================= FPS path (identical arithmetic to R7) ===========
        float* sXX = (float*)dynsm;                       // [PTS_PER_BLOCK]
        float* sYY = sXX + PTS_PER_BLOCK;
        float* sZZ = sYY + PTS_PER_BLOCK;
        u64*   sSlot = (u64*)(sZZ + PTS_PER_BLOCK);       // [2][NSLOT][4]

        const int gbase = b * PTS_PER_BLOCK;

        float mind[2 * PPT];
        u64   zp[PPT];

        // zero slots (tag 0 never matches iter >= 1)
        if (t < 256) { sSlot[t] = 0ull; sSlot[t + 256] = 0ull; }

        const float c0x = coord[0], c0y = coord[1], c0z = coord[2];
        float tmax = -1e30f;

#pragma unroll
        for (int k = 0; k < PPT; k++) {
            int p  = t + k * FPS_T;
            int i0 = gbase + 2 * p;
            int i1 = i0 + 1;
            float x0, y0, z0, x1, y1, z1, m0, m1;
            if (i0 < NPTS) {
                x0 = coord[3 * i0]; y0 = coord[3 * i0 + 1]; z0 = coord[3 * i0 + 2];
                m0 = d2_ref(x0, y0, z0, c0x, c0y, c0z);
            } else { x0 = y0 = z0 = 1e18f; m0 = -1.0f; }
            if (i1 < NPTS) {
                x1 = coord[3 * i1]; y1 = coord[3 * i1 + 1]; z1 = coord[3 * i1 + 2];
                m1 = d2_ref(x1, y1, z1, c0x, c0y, c0z);
            } else { x1 = y1 = z1 = 1e18f; m1 = -1.0f; }
            sXX[2 * p] = x0; sXX[2 * p + 1] = x1;
            sYY[2 * p] = y0; sYY[2 * p + 1] = y1;
            sZZ[2 * p] = z0; sZZ[2 * p + 1] = z1;
            zp[k] = f2_pack(z0, z1);
            mind[2 * k] = m0; mind[2 * k + 1] = m1;
            tmax = fmaxf(tmax, fmaxf(m0, m1));
        }

        int bidx = 0x7FFF;
#pragma unroll
        for (int k = 0; k < PPT; k++) {
            int g = gbase + 2 * (t + k * FPS_T);
            if (mind[2 * k] == tmax && g < bidx)           bidx = g;
            if (mind[2 * k + 1] == tmax && (g + 1) < bidx) bidx = g + 1;
        }

        if (b == 0 && t == 0) {
            st_rlx_i(&g_sel[0], 0);
            out[OFF_COORD + 0] = c0x; out[OFF_COORD + 1] = c0y; out[OFF_COORD + 2] = c0z;
        }
        __syncthreads();
        // all CTAs' slot-zeroing + smem tiles visible before any remote publish
        asm volatile("barrier.cluster.arrive.aligned;" ::: "memory");
        asm volatile("barrier.cluster.wait.aligned;" ::: "memory");

        const uint32_t slotBase = (uint32_t)__cvta_generic_to_shared(sSlot);
        const int sid = b * NWARP + warp;
        const uint32_t myOff = (uint32_t)sid * 32u;
        const int peer = lane >> 2, s = lane & 3;

        for (int i = 1; i < NDST; i++) {
            // --- warp-level candidate (val, first-idx) via 32-bit redux ---
            unsigned vb = __float_as_uint(fmaxf(tmax, 0.0f));
            unsigned wm = __reduce_max_sync(0xffffffffu, vb);
            unsigned inv = (vb == wm) ? (unsigned)(0x7FFF - bidx) : 0u;
            unsigned wi = __reduce_max_sync(0xffffffffu, inv);
            const int widx = 0x7FFF - (int)wi;
            const int li = widx - gbase;

            const uint32_t par = (uint32_t)(i & 1);
            const uint32_t parOff = par * (NSLOT * 32u);

            // --- publish key + winner coords to every CTA (1 store per lane) ---
            {
                u64 v;
                if (s == 0) {
                    v = ((u64)(unsigned)i << 47) | ((u64)wm << 15) | (u64)wi;
                } else {
                    float c = (s == 1) ? sXX[li] : (s == 2) ? sYY[li] : sZZ[li];
                    v = ((u64)(unsigned)i << 32) | (u64)__float_as_uint(c);
                }
                uint32_t la = slotBase + parOff + myOff + (uint32_t)s * 8u;
                st_remote(mapa_rank(la, (uint32_t)peer), v);
            }

            // --- poll all 64 keys (2 per lane), ballot until complete ---
            const uint32_t gbuf = slotBase + parOff;
            const uint32_t a0 = gbuf + (uint32_t)lane * 32u;
            const uint32_t a1 = a0 + 32u * 32u;
            u64 k0, k1;
            for (;;) {
                k0 = lds_rlx(a0); k1 = lds_rlx(a1);
                bool o = ((unsigned)(k0 >> 47) == (unsigned)i) &
                         ((unsigned)(k1 >> 47) == (unsigned)i);
                if (__all_sync(0xffffffffu, o)) break;
            }
            u64 k = (k0 > k1) ? k0 : k1;
            unsigned v32 = (unsigned)(k >> 15);
            unsigned i15 = (unsigned)(k & 0x7FFFu);
            unsigned vmax = __reduce_max_sync(0xffffffffu, v32);
            unsigned imax = __reduce_max_sync(0xffffffffu, (v32 == vmax) ? i15 : 0u);
            const int sel = 0x7FFF - (int)imax;

            // --- winner's coord slots (arrive with its key; tag-checked) ---
            const int wc = sel / PTS_PER_BLOCK;
            const int lp = (sel - wc * PTS_PER_BLOCK) >> 1;
            const int ww = (lp & (FPS_T - 1)) >> 5;
            const uint32_t cb = gbuf + (uint32_t)(wc * NWARP + ww) * 32u;
            u64 c1, c2, c3;
            for (;;) {
                c1 = lds_rlx(cb + 8u); c2 = lds_rlx(cb + 16u); c3 = lds_rlx(cb + 24u);
                bool o = ((unsigned)(c1 >> 32) == (unsigned)i) &
                         ((unsigned)(c2 >> 32) == (unsigned)i) &
                         ((unsigned)(c3 >> 32) == (unsigned)i);
                if (o) break;
            }
            const float cx = __uint_as_float((unsigned)c1);
            const float cy = __uint_as_float((unsigned)c2);
            const float cz = __uint_as_float((unsigned)c3);

            if (b == 0 && t == 0) {
                out[OFF_COORD + 3 * i]     = cx;
                out[OFF_COORD + 3 * i + 1] = cy;
                out[OFF_COORD + 3 * i + 2] = cz;
                st_rlx_i(&g_sel[i], sel);       // release point for ball warps
            }

            // --- update min distances (packed f32x2; exact rounding) ---
            const u64 ncx = f2_pack(-cx, -cx);
            const u64 ncy = f2_pack(-cy, -cy);
            const u64 ncz = f2_pack(-cz, -cz);
            float tA = -1e30f, tB = -1e30f;
#pragma unroll
            for (int kk = 0; kk < PPT; kk++) {
                int p = t + kk * FPS_T;
                u64 xx = *reinterpret_cast<const u64*>(&sXX[2 * p]);
                u64 yy = *reinterpret_cast<const u64*>(&sYY[2 * p]);
                u64 dx = f2_add(xx, ncx);
                u64 dy = f2_add(yy, ncy);
                u64 dz = f2_add(zp[kk], ncz);
                u64 d2 = f2_add(f2_add(f2_mul(dx, dx), f2_mul(dy, dy)), f2_mul(dz, dz));
                float2 d = f2_unpack(d2);
                mind[2 * kk]     = fminf(mind[2 * kk], d.x);
                mind[2 * kk + 1] = fminf(mind[2 * kk + 1], d.y);
                tA = fmaxf(tA, mind[2 * kk]);
                tB = fmaxf(tB, mind[2 * kk + 1]);
            }
            tmax = fmaxf(tA, tB);

            bidx = 0x7FFF;
#pragma unroll
            for (int kk = 0; kk < PPT; kk++) {
                int g = gbase + 2 * (t + kk * FPS_T);
                if (mind[2 * kk] == tmax && g < bidx)           bidx = g;
                if (mind[2 * kk + 1] == tmax && (g + 1) < bidx) bidx = g + 1;
            }
        }

        asm volatile("barrier.cluster.arrive.aligned;" ::: "memory");
        asm volatile("barrier.cluster.wait.aligned;" ::: "memory");
    } else {
        // ================= ball path: poll g_sel, ordered append ===========
        const float R2 = (float)(0.08 * 0.08);
        const int ballWarp = (b - FPS_B) * NWARP + warp;

        for (int d = ballWarp; d < NDST; d += BALL_WARPS) {
            int sel;
            if (lane == 0) {
                while ((sel = ld_rlx_i(&g_sel[d])) < 0) __nanosleep(200);
            }
            sel = __shfl_sync(0xffffffffu, sel, 0);

            const float cx = __ldg(coord + 3 * sel);
            const float cy = __ldg(coord + 3 * sel + 1);
            const float cz = __ldg(coord + 3 * sel + 2);
            const float sd = g_ssrc[sel];

            int cnt = 0;
            for (int j0 = 0; j0 < NPTS; j0 += 32) {
                const int j = j0 + lane;   // NPTS % 32 == 0, no tail
                float xj = coord[3 * j], yj = coord[3 * j + 1], zj = coord[3 * j + 2];
                float sj = g_ssrc[j];
                float dot = __fmaf_rn(cz, zj, __fmaf_rn(cy, yj, __fmul_rn(cx, xj)));
                float d2 = __fsub_rn(__fadd_rn(sd, sj), __fmul_rn(2.0f, dot));
                bool w = (d2 <= R2);
                unsigned bal = __ballot_sync(0xffffffffu, w);
                int pos = cnt + __popc(bal & ((1u << lane) - 1u));
                if (w && pos < KNB) sN[warp][pos] = j;
                cnt += __popc(bal);
                if (cnt >= KNB) break;
            }
            __syncwarp();

            const int deg = min(cnt, KNB);
            const int base = d * KNB;
            int nb = (lane < deg) ? sN[warp][lane] : -1;
            g_nbr[base + lane] = nb;
            out[OFF_ESRC + base + lane] = (float)nb;
            out[OFF_EDST + base + lane] = (lane < deg) ? (float)d : -1.0f;
            if (lane == 0) {
                g_deg[d] = deg;
                out[OFF_DEG + d] = (float)deg;
                out[OFF_BATCH + d] = (float)__ldg(batch + sel);
            }
            __syncwarp();
        }
    }
}

// ---------------- feature scatter-mean: one block (128 thr) per dst --------
__global__ void feat_kernel(const float* __restrict__ feat,
                            float* __restrict__ out) {
    __shared__ int sNbr[KNB];
    __shared__ int sDeg;
    const int d = blockIdx.x;
    const int tid = threadIdx.x;
    if (tid < KNB) sNbr[tid] = g_nbr[d * KNB + tid];
    if (tid == 0)  sDeg = g_deg[d];
    __syncthreads();
    const int dg = sDeg;
    float acc = 0.0f;
    for (int k = 0; k < dg; k++)
        acc = __fadd_rn(acc, feat[(size_t)sNbr[k] * 128 + tid]);
    out[OFF_FEAT + (size_t)d * 128 + tid] = acc / (float)max(dg, 1);
}

// ---------------- launch ----------------
extern "C" void kernel_launch(void* const* d_in, const int* in_sizes, int n_in,
                              void* d_out, int out_size) {
    const float* coord = (const float*)d_in[0];
    const float* feat  = (const float*)d_in[1];
    const int*   batch = (const int*)d_in[2];
    float* out = (float*)d_out;

    cudaFuncSetAttribute(fps_kernel,
                         cudaFuncAttributeMaxDynamicSharedMemorySize, DYN_SMEM);

    ssrc_kernel<<<(NPTS + 255) / 256, 256>>>(coord);
    fps_kernel<<<GRID_CTAS, FPS_T, DYN_SMEM>>>(coord, batch, out);
    feat_kernel<<<NDST, 128>>>(feat, out);
}